// round 5
// baseline (speedup 1.0000x reference)
#include <cuda_runtime.h>
#include <cuda_fp16.h>

#define DEV_INLINE __device__ __forceinline__

// ---------------- problem constants ----------------
constexpr int BATCH = 4;
constexpr int SEQ   = 2048;
constexpr int DIM   = 1024;            // D == DQKV
constexpr int MTOK  = BATCH * SEQ;     // 8192

// ---------------- GEMM tiling ----------------
constexpr int BM = 128, BN = 128, BK = 32, SPAD = 8;
constexpr int LDS = BK + SPAD;         // 40 halfs per smem row
constexpr int TILE_E = BM * LDS;       // elements per tile stage (A and B identical: BM==BN)
constexpr int WM = 64, WN = 32;        // warp tile (8 warps: 2 x 4)
constexpr int SMEM_PLAIN = 4 * TILE_E * 2;   // A,B x 2 stages (bytes) = 40960
constexpr int SMEM_SPLIT = 8 * TILE_E * 2;   // + Al,Bl            = 81920

// ---------------- scratch (static device allocations; no cudaMalloc) ----------------
__device__ __align__(16) __half g_xh[MTOK * DIM];            // 16 MB
__device__ __align__(16) __half g_xl[MTOK * DIM];            // 16 MB
__device__ __align__(16) __half g_wth[3 * DIM * DIM];        // Wt[n][k], n in [0,3072)
__device__ __align__(16) __half g_wtl[3 * DIM * DIM];
__device__ __align__(16) __half g_q[MTOK * DIM];             // fp16 Q  [b*S+i][d]
__device__ __align__(16) __half g_k[MTOK * DIM];             // fp16 K  [b*S+i][d]
__device__ __align__(16) __half g_vt[BATCH * DIM * SEQ];     // fp16 V^T [b][d][i]
__device__ __align__(16) float  g_s[(size_t)BATCH * SEQ * SEQ];  // scores fp32, 64 MB
__device__ __align__(16) __half g_p[(size_t)BATCH * SEQ * SEQ];  // softmax fp16, 32 MB

// ---------------- small PTX helpers ----------------
DEV_INLINE void cp16(unsigned dst, const void* src) {
    asm volatile("cp.async.cg.shared.global [%0], [%1], 16;\n" :: "r"(dst), "l"(src));
}
DEV_INLINE void cp_commit() { asm volatile("cp.async.commit_group;\n" ::: "memory"); }
template <int N> DEV_INLINE void cp_wait() {
    asm volatile("cp.async.wait_group %0;\n" :: "n"(N) : "memory");
}
DEV_INLINE void ldsm4(unsigned addr, unsigned& r0, unsigned& r1, unsigned& r2, unsigned& r3) {
    asm volatile("ldmatrix.sync.aligned.m8n8.x4.shared.b16 {%0,%1,%2,%3}, [%4];\n"
        : "=r"(r0), "=r"(r1), "=r"(r2), "=r"(r3) : "r"(addr));
}
DEV_INLINE void ldsm2(unsigned addr, unsigned& r0, unsigned& r1) {
    asm volatile("ldmatrix.sync.aligned.m8n8.x2.shared.b16 {%0,%1}, [%2];\n"
        : "=r"(r0), "=r"(r1) : "r"(addr));
}
DEV_INLINE void mma16816(float c[4], const unsigned a[4], const unsigned b[2]) {
    asm volatile(
        "mma.sync.aligned.m16n8k16.row.col.f32.f16.f16.f32 "
        "{%0,%1,%2,%3}, {%4,%5,%6,%7}, {%8,%9}, {%0,%1,%2,%3};\n"
        : "+f"(c[0]), "+f"(c[1]), "+f"(c[2]), "+f"(c[3])
        : "r"(a[0]), "r"(a[1]), "r"(a[2]), "r"(a[3]), "r"(b[0]), "r"(b[1]));
}

// ---------------- GEMM parameter block ----------------
struct GemmP {
    const __half* A;  const __half* Al;
    const __half* B;  const __half* Bl;
    float* C;
    __half* q; __half* k; __half* vt;
    long long sAz, sBz, sCz;   // per-batch (blockIdx.z) element strides
    int lda, ldb, ldc, K;
    float scale;
};

DEV_INLINE void store_qkv(const GemmP& p, int r, int c, float v) {
    __half h = __float2half(v);
    if (c < DIM) {
        p.q[(size_t)r * DIM + c] = h;
    } else if (c < 2 * DIM) {
        p.k[(size_t)r * DIM + (c - DIM)] = h;
    } else {
        int d = c - 2 * DIM;
        int b = r >> 11;             // r / SEQ
        int i = r & (SEQ - 1);
        p.vt[((size_t)b * DIM + d) * SEQ + i] = h;
    }
}

// MODE 0: QKV projection epilogue (fp16 Q/K + transposed V)
// MODE 1: scores epilogue (fp32 * scale)
// MODE 2: output epilogue (fp32)
template <int MODE, bool SPLIT>
__global__ __launch_bounds__(256, 1) void gemm_kernel(GemmP p) {
    extern __shared__ __half sm[];
    const unsigned su = (unsigned)__cvta_generic_to_shared(sm);

    const int tid = threadIdx.x;
    const int bm = blockIdx.y * BM;
    const int bn = blockIdx.x * BN;

    const __half* A  = p.A + (size_t)blockIdx.z * p.sAz;
    const __half* B  = p.B + (size_t)blockIdx.z * p.sBz;
    const __half* Al = SPLIT ? (p.Al + (size_t)blockIdx.z * p.sAz) : nullptr;
    const __half* Bl = SPLIT ? (p.Bl + (size_t)blockIdx.z * p.sBz) : nullptr;

    // gmem->smem: 512 16-byte chunks per tile, 2 per thread. chunk c: row=c>>2, colchunk=c&3.
    const int r0 = tid >> 2,         c0 = (tid & 3) * 8;
    const int r1 = (tid + 256) >> 2, c1 = ((tid + 256) & 3) * 8;

    auto load_stage = [&](int st, int k0) {
        const unsigned uA  = su + (unsigned)((0 * TILE_E + st * TILE_E) * 2);
        const unsigned uB  = su + (unsigned)((2 * TILE_E + st * TILE_E) * 2);
        cp16(uA + (r0 * LDS + c0) * 2, A + (size_t)(bm + r0) * p.lda + k0 + c0);
        cp16(uA + (r1 * LDS + c1) * 2, A + (size_t)(bm + r1) * p.lda + k0 + c1);
        cp16(uB + (r0 * LDS + c0) * 2, B + (size_t)(bn + r0) * p.ldb + k0 + c0);
        cp16(uB + (r1 * LDS + c1) * 2, B + (size_t)(bn + r1) * p.ldb + k0 + c1);
        if (SPLIT) {
            const unsigned uAl = su + (unsigned)((4 * TILE_E + st * TILE_E) * 2);
            const unsigned uBl = su + (unsigned)((6 * TILE_E + st * TILE_E) * 2);
            cp16(uAl + (r0 * LDS + c0) * 2, Al + (size_t)(bm + r0) * p.lda + k0 + c0);
            cp16(uAl + (r1 * LDS + c1) * 2, Al + (size_t)(bm + r1) * p.lda + k0 + c1);
            cp16(uBl + (r0 * LDS + c0) * 2, Bl + (size_t)(bn + r0) * p.ldb + k0 + c0);
            cp16(uBl + (r1 * LDS + c1) * 2, Bl + (size_t)(bn + r1) * p.ldb + k0 + c1);
        }
    };

    const int lane = tid & 31, wid = tid >> 5;
    const int wm0 = (wid & 1) * WM;     // 0 / 64
    const int wn0 = (wid >> 1) * WN;    // 0 / 32 / 64 / 96

    // fragment smem element offsets (stage- and kk-independent parts)
    int aoff[4], boff[4];
#pragma unroll
    for (int mt = 0; mt < 4; mt++)
        aoff[mt] = (wm0 + mt * 16 + (lane & 15)) * LDS + ((lane >> 4) << 3);
#pragma unroll
    for (int nt = 0; nt < 4; nt++)
        boff[nt] = (wn0 + nt * 8 + (lane & 7)) * LDS + (((lane >> 3) & 1) << 3);

    float acc[4][4][4];
#pragma unroll
    for (int mt = 0; mt < 4; mt++)
#pragma unroll
        for (int nt = 0; nt < 4; nt++)
#pragma unroll
            for (int i = 0; i < 4; i++) acc[mt][nt][i] = 0.0f;

    const int KT = p.K / BK;
    load_stage(0, 0);
    cp_commit();

    for (int kt = 0; kt < KT; kt++) {
        if (kt + 1 < KT) {
            load_stage((kt + 1) & 1, (kt + 1) * BK);
            cp_commit();
            cp_wait<1>();
        } else {
            cp_wait<0>();
        }
        __syncthreads();

        const int st = kt & 1;
        const unsigned uA  = su + (unsigned)((0 * TILE_E + st * TILE_E) * 2);
        const unsigned uB  = su + (unsigned)((2 * TILE_E + st * TILE_E) * 2);
        const unsigned uAl = su + (unsigned)((4 * TILE_E + st * TILE_E) * 2);
        const unsigned uBl = su + (unsigned)((6 * TILE_E + st * TILE_E) * 2);

#pragma unroll
        for (int kk = 0; kk < BK; kk += 16) {
            unsigned af[4][4], bf[4][2];
            unsigned afl[4][4], bfl[4][2];
#pragma unroll
            for (int mt = 0; mt < 4; mt++)
                ldsm4(uA + (unsigned)((aoff[mt] + kk) * 2),
                      af[mt][0], af[mt][1], af[mt][2], af[mt][3]);
#pragma unroll
            for (int nt = 0; nt < 4; nt++)
                ldsm2(uB + (unsigned)((boff[nt] + kk) * 2), bf[nt][0], bf[nt][1]);
            if (SPLIT) {
#pragma unroll
                for (int mt = 0; mt < 4; mt++)
                    ldsm4(uAl + (unsigned)((aoff[mt] + kk) * 2),
                          afl[mt][0], afl[mt][1], afl[mt][2], afl[mt][3]);
#pragma unroll
                for (int nt = 0; nt < 4; nt++)
                    ldsm2(uBl + (unsigned)((boff[nt] + kk) * 2), bfl[nt][0], bfl[nt][1]);
            }
#pragma unroll
            for (int mt = 0; mt < 4; mt++) {
#pragma unroll
                for (int nt = 0; nt < 4; nt++) {
                    mma16816(acc[mt][nt], af[mt], bf[nt]);
                    if (SPLIT) {
                        mma16816(acc[mt][nt], af[mt], bfl[nt]);   // hi * lo
                        mma16816(acc[mt][nt], afl[mt], bf[nt]);   // lo * hi
                    }
                }
            }
        }
        __syncthreads();
    }

    // ---------------- epilogue ----------------
    const int g = lane >> 2, tg = lane & 3;
#pragma unroll
    for (int mt = 0; mt < 4; mt++) {
#pragma unroll
        for (int nt = 0; nt < 4; nt++) {
            const int r = bm + wm0 + mt * 16 + g;
            const int c = bn + wn0 + nt * 8 + tg * 2;
            const float* a = acc[mt][nt];
            if (MODE == 1 || MODE == 2) {
                float* C = p.C + (size_t)blockIdx.z * p.sCz;
                C[(size_t)r * p.ldc + c]           = a[0] * p.scale;
                C[(size_t)r * p.ldc + c + 1]       = a[1] * p.scale;
                C[(size_t)(r + 8) * p.ldc + c]     = a[2] * p.scale;
                C[(size_t)(r + 8) * p.ldc + c + 1] = a[3] * p.scale;
            } else {
                store_qkv(p, r,     c,     a[0]);
                store_qkv(p, r,     c + 1, a[1]);
                store_qkv(p, r + 8, c,     a[2]);
                store_qkv(p, r + 8, c + 1, a[3]);
            }
        }
    }
}

// ---------------- prep: x -> fp16 hi/lo split ----------------
__global__ void convert_x_kernel(const float* __restrict__ x,
                                 __half* __restrict__ xh, __half* __restrict__ xl) {
    size_t i = (size_t)blockIdx.x * blockDim.x + threadIdx.x;   // per float4
    float4 v = ((const float4*)x)[i];
    __half h0 = __float2half(v.x), h1 = __float2half(v.y);
    __half h2 = __float2half(v.z), h3 = __float2half(v.w);
    ((__half2*)xh)[2 * i]     = __halves2half2(h0, h1);
    ((__half2*)xh)[2 * i + 1] = __halves2half2(h2, h3);
    __half l0 = __float2half(v.x - __half2float(h0));
    __half l1 = __float2half(v.y - __half2float(h1));
    __half l2 = __float2half(v.z - __half2float(h2));
    __half l3 = __float2half(v.w - __half2float(h3));
    ((__half2*)xl)[2 * i]     = __halves2half2(l0, l1);
    ((__half2*)xl)[2 * i + 1] = __halves2half2(l2, l3);
}

// ---------------- prep: w[k][n] -> Wt[n][k] fp16 hi/lo split (tiled transpose) --------
__global__ void prep_w_kernel(const float* __restrict__ w,
                              __half* __restrict__ wh, __half* __restrict__ wl) {
    __shared__ float t[32][33];
    const int k0 = blockIdx.y * 32, n0 = blockIdx.x * 32;
#pragma unroll
    for (int r = 0; r < 32; r += 8)
        t[threadIdx.y + r][threadIdx.x] =
            w[(size_t)(k0 + threadIdx.y + r) * DIM + n0 + threadIdx.x];
    __syncthreads();
#pragma unroll
    for (int r = 0; r < 32; r += 8) {
        const int n = n0 + threadIdx.y + r;
        const int k = k0 + threadIdx.x;
        const float v = t[threadIdx.x][threadIdx.y + r];
        __half h = __float2half(v);
        wh[(size_t)n * DIM + k] = h;
        wl[(size_t)n * DIM + k] = __float2half(v - __half2float(h));
    }
}

// ---------------- softmax: rows of 2048, fp32 in -> fp16 probs ----------------
__global__ __launch_bounds__(256) void softmax_kernel(const float* __restrict__ S,
                                                      __half* __restrict__ P) {
    __shared__ float red[8];
    const size_t row = blockIdx.x;
    const float* sr = S + row * SEQ;
    __half* pr = P + row * SEQ;
    const int tid = threadIdx.x;

    float v[8];
    float m = -1e30f;
#pragma unroll
    for (int j = 0; j < 8; j++) {
        v[j] = sr[tid + j * 256];
        m = fmaxf(m, v[j]);
    }
#pragma unroll
    for (int o = 16; o > 0; o >>= 1) m = fmaxf(m, __shfl_xor_sync(0xffffffffu, m, o));
    if ((tid & 31) == 0) red[tid >> 5] = m;
    __syncthreads();
    float M = red[0];
#pragma unroll
    for (int wv = 1; wv < 8; wv++) M = fmaxf(M, red[wv]);
    __syncthreads();

    float sum = 0.0f;
#pragma unroll
    for (int j = 0; j < 8; j++) {
        v[j] = __expf(v[j] - M);
        sum += v[j];
    }
#pragma unroll
    for (int o = 16; o > 0; o >>= 1) sum += __shfl_xor_sync(0xffffffffu, sum, o);
    if ((tid & 31) == 0) red[tid >> 5] = sum;
    __syncthreads();
    float tot = 0.0f;
#pragma unroll
    for (int wv = 0; wv < 8; wv++) tot += red[wv];
    const float inv = 1.0f / tot;
#pragma unroll
    for (int j = 0; j < 8; j++) pr[tid + j * 256] = __float2half(v[j] * inv);
}

// ---------------- launch ----------------
extern "C" void kernel_launch(void* const* d_in, const int* in_sizes, int n_in,
                              void* d_out, int out_size) {
    const float* x = (const float*)d_in[0];
    const float* w[3] = { (const float*)d_in[1], (const float*)d_in[2], (const float*)d_in[3] };
    float* out = (float*)d_out;

    void *xh, *xl, *wth, *wtl, *q, *k, *vt, *s, *pbuf;
    cudaGetSymbolAddress(&xh, g_xh);
    cudaGetSymbolAddress(&xl, g_xl);
    cudaGetSymbolAddress(&wth, g_wth);
    cudaGetSymbolAddress(&wtl, g_wtl);
    cudaGetSymbolAddress(&q, g_q);
    cudaGetSymbolAddress(&k, g_k);
    cudaGetSymbolAddress(&vt, g_vt);
    cudaGetSymbolAddress(&s, g_s);
    cudaGetSymbolAddress(&pbuf, g_p);

    cudaFuncSetAttribute(gemm_kernel<0, true>,
                         cudaFuncAttributeMaxDynamicSharedMemorySize, SMEM_SPLIT);
    cudaFuncSetAttribute(gemm_kernel<1, false>,
                         cudaFuncAttributeMaxDynamicSharedMemorySize, SMEM_PLAIN);
    cudaFuncSetAttribute(gemm_kernel<2, false>,
                         cudaFuncAttributeMaxDynamicSharedMemorySize, SMEM_PLAIN);

    // 1) input split to fp16 hi/lo
    convert_x_kernel<<<(MTOK * DIM / 4) / 256, 256>>>(x, (__half*)xh, (__half*)xl);

    // 2) weight transpose + split (3 weights into concatenated Wt[3072][1024])
    for (int i = 0; i < 3; i++)
        prep_w_kernel<<<dim3(32, 32), dim3(32, 8)>>>(
            w[i], (__half*)wth + (size_t)i * DIM * DIM, (__half*)wtl + (size_t)i * DIM * DIM);

    // 3) fused QKV projection: [8192,1024] x [1024,3072], split-fp16 (fp32-accurate)
    {
        GemmP p{};
        p.A = (__half*)xh;  p.Al = (__half*)xl;
        p.B = (__half*)wth; p.Bl = (__half*)wtl;
        p.q = (__half*)q; p.k = (__half*)k; p.vt = (__half*)vt;
        p.lda = DIM; p.ldb = DIM; p.K = DIM; p.scale = 1.0f;
        gemm_kernel<0, true><<<dim3(3 * DIM / BN, MTOK / BM, 1), 256, SMEM_SPLIT>>>(p);
    }

    // 4) scores = Q K^T / 32 (per batch), fp16 inputs, fp32 out
    {
        GemmP p{};
        p.A = (__half*)q; p.B = (__half*)k; p.C = (float*)s;
        p.sAz = (long long)SEQ * DIM; p.sBz = (long long)SEQ * DIM;
        p.sCz = (long long)SEQ * SEQ;
        p.lda = DIM; p.ldb = DIM; p.ldc = SEQ; p.K = DIM;
        p.scale = 1.0f / 32.0f;
        gemm_kernel<1, false><<<dim3(SEQ / BN, SEQ / BM, BATCH), 256, SMEM_PLAIN>>>(p);
    }

    // 5) softmax rows -> fp16 P
    softmax_kernel<<<BATCH * SEQ, 256>>>((const float*)s, (__half*)pbuf);

    // 6) out = P V (per batch): A = P [2048,2048], Bcol = Vt[d][j], fp32 out
    {
        GemmP p{};
        p.A = (__half*)pbuf; p.B = (__half*)vt; p.C = out;
        p.sAz = (long long)SEQ * SEQ; p.sBz = (long long)DIM * SEQ;
        p.sCz = (long long)SEQ * DIM;
        p.lda = SEQ; p.ldb = SEQ; p.ldc = DIM; p.K = SEQ;
        p.scale = 1.0f;
        gemm_kernel<2, false><<<dim3(DIM / BN, SEQ / BM, BATCH), 256, SMEM_PLAIN>>>(p);
    }
}